// round 4
// baseline (speedup 1.0000x reference)
#include <cuda_runtime.h>
#include <cstdint>

// Fixed problem shape: B=1, N=768, C_IN=C_OUT=16, R=8
#define N_PTS  768
#define A_GRP  2                        // output rows per block
#define N_GRPS (N_PTS / A_GRP)          // 384 blocks, one group each
#define NWARPS 8
#define NTHR   256
#define ITERS  (N_PTS / (NWARPS * 4))   // 24 (4 b's per warp-iteration via p)

typedef unsigned long long ull;

// smem float offsets
#define OFF_GEOM  12288                 // sFeatT: 6144 ull = 12288 floats (49152B)
#define OFF_RED   15360                 // sGeom : 768 float4 = 3072 floats
#define OFF_GBUF  17664                 // sRed  : 1152 ull = 2304 floats
#define SMEM_FLOATS 17920               // + sGbuf 256 floats -> 71680 B, 3 blocks/SM

// ---------------------------------------------------------------------------
// One block == one group of A_GRP=2 output rows.
//   Lane = p*8 + r (p: b-slot 0..3, r: RBF basis 0..7).
//   Features TRANSPOSED: sFeatT[k][b] (k = ull chunk 0..7) -> p-lanes hit
//   banks {2b,2b+2,2b+4,2b+6}: conflict-free, no padding.
//   Accumulation: packed fma.rn.f32x2 (8 inst per a-row for 16 channels).
//   3 blocks resident per SM (24 warps) to cover the sqrt->ex2->fma chain.
// ---------------------------------------------------------------------------
__global__ void __launch_bounds__(NTHR, 3) conv_fused(
    const float* __restrict__ feat,    // [768,16]
    const float* __restrict__ geom,    // [768,3]
    const float* __restrict__ W,       // [8,16,16]
    const float* __restrict__ mu,      // [8]
    const float* __restrict__ gamma,   // [8]
    float scale,
    float* __restrict__ out)           // [768,16]
{
    extern __shared__ float smem[];
    ull*    sFeatT = (ull*)smem;
    float4* sGeom  = (float4*)(smem + OFF_GEOM);
    ull*    sRed   = (ull*)(smem + OFF_RED);     // [ai][r][warp(pad 9)][8 ull]
    float*  sGbuf  = smem + OFF_GBUF;            // [ai][128]

    const int tid = threadIdx.x;

    // ---- fill shared ----
    const ull* featU = (const ull*)feat;         // 768*8 ull
    for (int i = tid; i < N_PTS * 8; i += NTHR) {
        int b = i >> 3, k = i & 7;
        sFeatT[k * N_PTS + b] = featU[i];
    }
    for (int b = tid; b < N_PTS; b += NTHR)
        sGeom[b] = make_float4(geom[3 * b], geom[3 * b + 1], geom[3 * b + 2], 0.f);
    __syncthreads();

    const int lane = tid & 31;
    const int warp = tid >> 5;
    const int r    = lane & 7;
    const int p    = lane >> 3;

    // RBF: pw = -(kr*d + mr)^2 = -gamma*log2(e)*(d-mu)^2
    const float kr = sqrtf(__ldg(gamma + r) * 1.44269504088896f);
    const float mr = -__ldg(mu + r) * kr;

    const int a0 = blockIdx.x * A_GRP;

    float gax[A_GRP], gay[A_GRP], gaz[A_GRP];
    #pragma unroll
    for (int ai = 0; ai < A_GRP; ai++) {
        float4 ga = sGeom[a0 + ai];
        gax[ai] = ga.x; gay[ai] = ga.y; gaz[ai] = ga.z;
    }

    ull acc[A_GRP][8];
    #pragma unroll
    for (int ai = 0; ai < A_GRP; ai++)
        #pragma unroll
        for (int k = 0; k < 8; k++) acc[ai][k] = 0ull;

    const int bbase = warp * 4 + p;

    #pragma unroll 4
    for (int it = 0; it < ITERS; it++) {
        const int b = bbase + it * 32;
        const float4 gb = sGeom[b];
        ull rv[8];
        #pragma unroll
        for (int k = 0; k < 8; k++) rv[k] = sFeatT[k * N_PTS + b];

        #pragma unroll
        for (int ai = 0; ai < A_GRP; ai++) {
            float dx = gb.x - gax[ai];
            float dy = gb.y - gay[ai];
            float dz = gb.z - gaz[ai];
            float d2 = fmaf(dx, dx, 1e-9f);
            d2 = fmaf(dy, dy, d2);
            d2 = fmaf(dz, dz, d2);
            float d;
            asm("sqrt.approx.f32 %0, %1;" : "=f"(d) : "f"(d2));
            float v  = fmaf(d, kr, mr);
            float pw = v * (-v);
            float e;
            asm("ex2.approx.f32 %0, %1;" : "=f"(e) : "f"(pw));
            ull e2;
            asm("mov.b64 %0, {%1, %1};" : "=l"(e2) : "f"(e));
            #pragma unroll
            for (int k = 0; k < 8; k++)
                asm("fma.rn.f32x2 %0, %1, %2, %0;"
                    : "+l"(acc[ai][k]) : "l"(rv[k]), "l"(e2));
        }
    }

    // ---- reduce over p (lane bits 3,4), packed ----
    #pragma unroll
    for (int ai = 0; ai < A_GRP; ai++)
        #pragma unroll
        for (int k = 0; k < 8; k++) {
            ull o = __shfl_xor_sync(0xffffffffu, acc[ai][k], 8);
            asm("add.rn.f32x2 %0, %0, %1;" : "+l"(acc[ai][k]) : "l"(o));
            o = __shfl_xor_sync(0xffffffffu, acc[ai][k], 16);
            asm("add.rn.f32x2 %0, %0, %1;" : "+l"(acc[ai][k]) : "l"(o));
        }

    // ---- per-warp partials: sRed[ai][r][warp][8 ull] (warp-dim padded to 9)
    if (p == 0) {
        #pragma unroll
        for (int ai = 0; ai < A_GRP; ai++) {
            ull* dst = sRed + ((ai * 8 + r) * 9 + warp) * 8;
            #pragma unroll
            for (int k = 0; k < 8; k++) dst[k] = acc[ai][k];
        }
    }
    __syncthreads();

    // ---- cross-warp reduce + W contraction: warp ai owns row a0+ai ----
    if (warp < A_GRP) {
        const int ai = warp;
        const int rr = lane >> 2;
        const int jp = (lane & 3) * 2;           // ull offset in 8-ull row
        ull s0 = 0ull, s1 = 0ull;
        #pragma unroll
        for (int w = 0; w < NWARPS; w++) {
            const ull* src = sRed + ((ai * 8 + rr) * 9 + w) * 8 + jp;
            asm("add.rn.f32x2 %0, %0, %1;" : "+l"(s0) : "l"(src[0]));
            asm("add.rn.f32x2 %0, %0, %1;" : "+l"(s1) : "l"(src[1]));
        }
        ull* gdst = (ull*)(sGbuf + ai * 128);
        gdst[lane * 2]     = s0;                 // ull idx 2*lane == rr*8 + jp
        gdst[lane * 2 + 1] = s1;
        __syncwarp();

        if (lane < 16) {
            const int i = lane;
            float accum = 0.f;
            const float4* wv = (const float4*)W;         // global, via L1/L2
            const float4* gv = (const float4*)(sGbuf + ai * 128);
            #pragma unroll
            for (int r2 = 0; r2 < 8; r2++)
                #pragma unroll
                for (int c = 0; c < 4; c++) {
                    float4 w4 = __ldg(wv + (r2 * 16 + i) * 4 + c);
                    float4 g4 = gv[r2 * 4 + c];
                    accum = fmaf(w4.x, g4.x, accum);
                    accum = fmaf(w4.y, g4.y, accum);
                    accum = fmaf(w4.z, g4.z, accum);
                    accum = fmaf(w4.w, g4.w, accum);
                }
            out[(a0 + ai) * 16 + i] = accum * scale;
        }
    }
}

// ---------------------------------------------------------------------------
// Launch: single kernel, 384 blocks (3 resident per SM), graph-capturable.
// ---------------------------------------------------------------------------
extern "C" void kernel_launch(void* const* d_in, const int* in_sizes, int n_in,
                              void* d_out, int out_size)
{
    const float* feat  = (const float*)d_in[0];   // [1,768,16]
    const float* geom  = (const float*)d_in[1];   // [1,768,3]
    const float* W     = (const float*)d_in[2];   // [8,16,16]
    const float* mu    = (const float*)d_in[3];   // [8]
    const float* gamma = (const float*)d_in[4];   // [8]
    float* out = (float*)d_out;

    const int n_norm = in_sizes[1] / 3;           // N, host-side
    const float scale = 1.0f / sqrtf((float)n_norm);

    const size_t smem_bytes = (size_t)SMEM_FLOATS * sizeof(float);  // 71680
    cudaFuncSetAttribute(conv_fused,
                         cudaFuncAttributeMaxDynamicSharedMemorySize,
                         (int)smem_bytes);

    conv_fused<<<N_GRPS, NTHR, smem_bytes>>>(feat, geom, W, mu, gamma, scale, out);
}

// round 6
// speedup vs baseline: 1.1345x; 1.1345x over previous
#include <cuda_runtime.h>
#include <cuda_bf16.h>
#include <cstdint>

// Fixed shape: B=1, N=768, C_IN=C_OUT=16, R=8
#define NPTS   768
#define NTILES 384          // M-tiles of 16 rows (2 a's x 8 r); one CTA each
#define NTHR   256

typedef unsigned int u32;

// Global pre-split features, transposed: featT[j][b], bf16 hi + lo (24KB each).
__device__ __nv_bfloat16 g_fhi[16 * NPTS];
__device__ __nv_bfloat16 g_flo[16 * NPTS];

__device__ __forceinline__ u32 pack_bf16x2(float lo, float hi) {
    u32 d;
    asm("cvt.rn.bf16x2.f32 %0, %1, %2;" : "=r"(d) : "f"(hi), "f"(lo));
    return d;
}
__device__ __forceinline__ float ex2f(float x) {
    float e;
    asm("ex2.approx.f32 %0, %1;" : "=f"(e) : "f"(x));
    return e;
}
__device__ __forceinline__ float sqrt_apx(float x) {
    float s;
    asm("sqrt.approx.f32 %0, %1;" : "=f"(s) : "f"(x));
    return s;
}
// D(16x8,f32) += A(16x16,row,bf16) * B(16x8,col,bf16)
__device__ __forceinline__ void mma16816(float& c0, float& c1, float& c2, float& c3,
                                         u32 a0, u32 a1, u32 a2, u32 a3,
                                         u32 b0, u32 b1) {
    asm("mma.sync.aligned.m16n8k16.row.col.f32.bf16.bf16.f32 "
        "{%0,%1,%2,%3}, {%4,%5,%6,%7}, {%8,%9}, {%0,%1,%2,%3};"
        : "+f"(c0), "+f"(c1), "+f"(c2), "+f"(c3)
        : "r"(a0), "r"(a1), "r"(a2), "r"(a3), "r"(b0), "r"(b1));
}

// ---------------------------------------------------------------------------
// Prep: split feat[b][j] fp32 -> featT_hi/lo[j][b] bf16 (transposed, global).
// 3072 threads, each produces one 4-b chunk (u64 store) for hi and lo.
// ---------------------------------------------------------------------------
__global__ void __launch_bounds__(NTHR) conv_prep(const float* __restrict__ feat)
{
    const int idx = blockIdx.x * NTHR + threadIdx.x;      // 0..3071
    const int j  = idx / 192;
    const int b4 = (idx % 192) * 4;
    float f[4];
    #pragma unroll
    for (int q = 0; q < 4; q++) f[q] = __ldg(&feat[(b4 + q) * 16 + j]);
    float h[4], l[4];
    #pragma unroll
    for (int q = 0; q < 4; q++) {
        h[q] = __bfloat162float(__float2bfloat16(f[q]));
        l[q] = f[q] - h[q];
    }
    const u32 h01 = pack_bf16x2(h[0], h[1]);
    const u32 h23 = pack_bf16x2(h[2], h[3]);
    const u32 l01 = pack_bf16x2(l[0], l[1]);
    const u32 l23 = pack_bf16x2(l[2], l[3]);
    const size_t o = (size_t)j * NPTS + b4;               // bf16 elem index, 8B-aligned
    *(uint2*)((char*)g_fhi + o * 2) = make_uint2(h01, h23);
    *(uint2*)((char*)g_flo + o * 2) = make_uint2(l01, l23);
}

// ---------------------------------------------------------------------------
// Main: CTA = M-tile of 16 rows = a-pair (a0, a0+1) x 8 RBF bases.
//   Fragment row g   -> (a_local=0, r=g);  row g+8 -> (a_local=1, r=g).
//   Warp w covers K slice [w*96, w*96+96) in 6 ksteps of 16.
//   Per kstep: gen A fragment (rbf hi/lo) from smem distances, LDG B frags
//   from global featT hi/lo, 6 HMMA (hi*hi, lo*hi, hi*lo) x 2 n-tiles.
//   Epilogue: smem reduce over 8 warps, W-contract, write out directly.
// ---------------------------------------------------------------------------
__global__ void __launch_bounds__(NTHR, 3) conv_main(
    const float* __restrict__ geom,    // [768,3]
    const float* __restrict__ W,       // [8,16,16]
    const float* __restrict__ mu,      // [8]
    const float* __restrict__ gamma,   // [8]
    float scale,
    float* __restrict__ out)           // [768,16]
{
    __shared__ float sD[2 * NPTS];     // distances d[a_local][b]
    __shared__ float sRed[8 * 256];    // per-warp C tiles [w][row][col]
    __shared__ float sG[256];          // reduced G [row][col]

    const int tid  = threadIdx.x;
    const int lane = tid & 31;
    const int warp = tid >> 5;
    const int a0   = blockIdx.x * 2;

    // ---- distances: 1536 values, 6 per thread ----
    {
        const float g0x = __ldg(&geom[a0 * 3]),       g0y = __ldg(&geom[a0 * 3 + 1]),
                    g0z = __ldg(&geom[a0 * 3 + 2]);
        const float g1x = __ldg(&geom[a0 * 3 + 3]),   g1y = __ldg(&geom[a0 * 3 + 4]),
                    g1z = __ldg(&geom[a0 * 3 + 5]);
        #pragma unroll
        for (int q = 0; q < 6; q++) {
            const int v  = tid + q * NTHR;            // 0..1535
            const int aL = v >= NPTS;
            const int b  = v - aL * NPTS;
            const float bx = __ldg(&geom[b * 3]);
            const float by = __ldg(&geom[b * 3 + 1]);
            const float bz = __ldg(&geom[b * 3 + 2]);
            const float dx = bx - (aL ? g1x : g0x);
            const float dy = by - (aL ? g1y : g0y);
            const float dz = bz - (aL ? g1z : g0z);
            float d2 = fmaf(dx, dx, 1e-9f);
            d2 = fmaf(dy, dy, d2);
            d2 = fmaf(dz, dz, d2);
            sD[v] = sqrt_apx(d2);
        }
    }
    __syncthreads();

    const int g = lane >> 2;           // fragment group = r
    const int t = lane & 3;
    const int c = t * 2;

    // RBF consts for this lane's r=g:  pw = -(kr*d + mr)^2
    const float kr = sqrt_apx(__ldg(gamma + g) * 1.44269504088896f);
    const float mr = -__ldg(mu + g) * kr;

    float acc[8];                      // [ntile(2)][4]
    #pragma unroll
    for (int k = 0; k < 8; k++) acc[k] = 0.f;

    const char* fhB = (const char*)g_fhi;
    const char* flB = (const char*)g_flo;

    #pragma unroll
    for (int s = 0; s < 6; s++) {
        const int kb = warp * 96 + s * 16 + c;        // absolute k for cols c,c+1

        // distances for the 8 A-fragment positions
        const float2 d00 = *(const float2*)&sD[kb];            // row g   , cols c,c+1
        const float2 d01 = *(const float2*)&sD[kb + 8];        // row g   , cols c+8,c+9
        const float2 d10 = *(const float2*)&sD[NPTS + kb];     // row g+8
        const float2 d11 = *(const float2*)&sD[NPTS + kb + 8];

        float v;
        v = fmaf(d00.x, kr, mr); const float e00x = ex2f(v * (-v));
        v = fmaf(d00.y, kr, mr); const float e00y = ex2f(v * (-v));
        v = fmaf(d10.x, kr, mr); const float e10x = ex2f(v * (-v));
        v = fmaf(d10.y, kr, mr); const float e10y = ex2f(v * (-v));
        v = fmaf(d01.x, kr, mr); const float e01x = ex2f(v * (-v));
        v = fmaf(d01.y, kr, mr); const float e01y = ex2f(v * (-v));
        v = fmaf(d11.x, kr, mr); const float e11x = ex2f(v * (-v));
        v = fmaf(d11.y, kr, mr); const float e11y = ex2f(v * (-v));

        // A hi fragments (PTX m16n8k16 layout: a0=row g lo-k, a1=row g+8 lo-k,
        //                 a2=row g hi-k, a3=row g+8 hi-k)
        const u32 ah0 = pack_bf16x2(e00x, e00y);
        const u32 ah1 = pack_bf16x2(e10x, e10y);
        const u32 ah2 = pack_bf16x2(e01x, e01y);
        const u32 ah3 = pack_bf16x2(e11x, e11y);

        // A lo fragments: residual vs bf16(hi)
        const u32 al0 = pack_bf16x2(e00x - __uint_as_float(ah0 << 16),
                                    e00y - __uint_as_float(ah0 & 0xFFFF0000u));
        const u32 al1 = pack_bf16x2(e10x - __uint_as_float(ah1 << 16),
                                    e10y - __uint_as_float(ah1 & 0xFFFF0000u));
        const u32 al2 = pack_bf16x2(e01x - __uint_as_float(ah2 << 16),
                                    e01y - __uint_as_float(ah2 & 0xFFFF0000u));
        const u32 al3 = pack_bf16x2(e11x - __uint_as_float(ah3 << 16),
                                    e11y - __uint_as_float(ah3 & 0xFFFF0000u));

        // B fragments: col n = g (+8 for ntile1); reg0 = k lo-half, reg1 = k hi-half
        const size_t i0 = ((size_t)g * NPTS + kb) * 2;         // bytes
        const size_t i1 = i0 + (size_t)8 * NPTS * 2;
        const u32 bh00 = *(const u32*)(fhB + i0);
        const u32 bh01 = *(const u32*)(fhB + i0 + 16);
        const u32 bh10 = *(const u32*)(fhB + i1);
        const u32 bh11 = *(const u32*)(fhB + i1 + 16);
        const u32 bl00 = *(const u32*)(flB + i0);
        const u32 bl01 = *(const u32*)(flB + i0 + 16);
        const u32 bl10 = *(const u32*)(flB + i1);
        const u32 bl11 = *(const u32*)(flB + i1 + 16);

        mma16816(acc[0], acc[1], acc[2], acc[3], ah0, ah1, ah2, ah3, bh00, bh01);
        mma16816(acc[4], acc[5], acc[6], acc[7], ah0, ah1, ah2, ah3, bh10, bh11);
        mma16816(acc[0], acc[1], acc[2], acc[3], al0, al1, al2, al3, bh00, bh01);
        mma16816(acc[4], acc[5], acc[6], acc[7], al0, al1, al2, al3, bh10, bh11);
        mma16816(acc[0], acc[1], acc[2], acc[3], ah0, ah1, ah2, ah3, bl00, bl01);
        mma16816(acc[4], acc[5], acc[6], acc[7], ah0, ah1, ah2, ah3, bl10, bl11);
    }

    // ---- stash per-warp C tile: sRed[w][row][col] ----
    // C layout: c0={g,c} c1={g,c+1} c2={g+8,c} c3={g+8,c+1}; ntile1 at col+8.
    {
        float* rb = sRed + warp * 256;
        *(float2*)&rb[g * 16 + c]            = make_float2(acc[0], acc[1]);
        *(float2*)&rb[(g + 8) * 16 + c]      = make_float2(acc[2], acc[3]);
        *(float2*)&rb[g * 16 + 8 + c]        = make_float2(acc[4], acc[5]);
        *(float2*)&rb[(g + 8) * 16 + 8 + c]  = make_float2(acc[6], acc[7]);
    }
    __syncthreads();

    // ---- reduce over 8 warps: thread tid owns (row, col) = (tid/16, tid%16)
    {
        float s = 0.f;
        #pragma unroll
        for (int w = 0; w < 8; w++) s += sRed[w * 256 + tid];
        sG[tid] = s;                   // G[row=a_local*8+r][col=j]... row g<->r
    }
    __syncthreads();

    // ---- W contraction: thread = (a_local, i, r); reduce r via shfl ----
    {
        const int r2 = tid & 7;
        const int i  = (tid >> 3) & 15;
        const int aL = tid >> 7;
        // G row index for (aL, r2) is row = aL*8 + r2; sG stride 16.
        const float* gp = sG + (aL * 8 + r2) * 16;
        const float4* wp = (const float4*)W + r2 * 64 + i * 4;
        float a = 0.f;
        #pragma unroll
        for (int q = 0; q < 4; q++) {
            const float4 g4 = *(const float4*)(gp + q * 4);
            const float4 w4 = __ldg(wp + q);
            a = fmaf(w4.x, g4.x, a);
            a = fmaf(w4.y, g4.y, a);
            a = fmaf(w4.z, g4.z, a);
            a = fmaf(w4.w, g4.w, a);
        }
        a += __shfl_xor_sync(0xffffffffu, a, 1);
        a += __shfl_xor_sync(0xffffffffu, a, 2);
        a += __shfl_xor_sync(0xffffffffu, a, 4);
        if (r2 == 0) out[(a0 + aL) * 16 + i] = a * scale;
    }
}

// ---------------------------------------------------------------------------
extern "C" void kernel_launch(void* const* d_in, const int* in_sizes, int n_in,
                              void* d_out, int out_size)
{
    const float* feat  = (const float*)d_in[0];   // [1,768,16]
    const float* geom  = (const float*)d_in[1];   // [1,768,3]
    const float* W     = (const float*)d_in[2];   // [8,16,16]
    const float* mu    = (const float*)d_in[3];   // [8]
    const float* gamma = (const float*)d_in[4];   // [8]
    float* out = (float*)d_out;

    const int n_norm = in_sizes[1] / 3;
    const float scale = 1.0f / sqrtf((float)n_norm);

    conv_prep<<<12, NTHR>>>(feat);
    conv_main<<<NTILES, NTHR>>>(geom, W, mu, gamma, scale, out);
}

// round 7
// speedup vs baseline: 1.2909x; 1.1379x over previous
#include <cuda_runtime.h>
#include <cuda_bf16.h>
#include <cstdint>

// Fixed shape: B=1, N=768, C_IN=C_OUT=16, R=8
#define NPTS   768
#define NTILES 384          // M-tiles of 16 rows (2 a's x 8 r); one CTA each
#define NTHR   256

typedef unsigned int u32;

// Global pre-split features, transposed: featT[j][b], bf16 hi + lo (24KB each).
__device__ __nv_bfloat16 g_fhi[16 * NPTS];
__device__ __nv_bfloat16 g_flo[16 * NPTS];

__device__ __forceinline__ u32 pack_bf16x2(float lo, float hi) {
    u32 d;
    asm("cvt.rn.bf16x2.f32 %0, %1, %2;" : "=r"(d) : "f"(hi), "f"(lo));
    return d;
}
__device__ __forceinline__ float ex2f(float x) {
    float e;
    asm("ex2.approx.f32 %0, %1;" : "=f"(e) : "f"(x));
    return e;
}
__device__ __forceinline__ float sqrt_apx(float x) {
    float s;
    asm("sqrt.approx.f32 %0, %1;" : "=f"(s) : "f"(x));
    return s;
}
// D(16x8,f32) += A(16x16,row,bf16) * B(16x8,col,bf16)
__device__ __forceinline__ void mma16816(float& c0, float& c1, float& c2, float& c3,
                                         u32 a0, u32 a1, u32 a2, u32 a3,
                                         u32 b0, u32 b1) {
    asm("mma.sync.aligned.m16n8k16.row.col.f32.bf16.bf16.f32 "
        "{%0,%1,%2,%3}, {%4,%5,%6,%7}, {%8,%9}, {%0,%1,%2,%3};"
        : "+f"(c0), "+f"(c1), "+f"(c2), "+f"(c3)
        : "r"(a0), "r"(a1), "r"(a2), "r"(a3), "r"(b0), "r"(b1));
}

// ---------------------------------------------------------------------------
// Prep: split feat[b][j] fp32 -> featT_hi/lo[j][b] bf16 (transposed, global).
// ---------------------------------------------------------------------------
__global__ void __launch_bounds__(NTHR) conv_prep(const float* __restrict__ feat)
{
    const int idx = blockIdx.x * NTHR + threadIdx.x;      // 0..3071
    const int j  = idx / 192;
    const int b4 = (idx % 192) * 4;
    float f[4];
    #pragma unroll
    for (int q = 0; q < 4; q++) f[q] = __ldg(&feat[(b4 + q) * 16 + j]);
    float h[4], l[4];
    #pragma unroll
    for (int q = 0; q < 4; q++) {
        h[q] = __bfloat162float(__float2bfloat16(f[q]));
        l[q] = f[q] - h[q];
    }
    const u32 h01 = pack_bf16x2(h[0], h[1]);
    const u32 h23 = pack_bf16x2(h[2], h[3]);
    const u32 l01 = pack_bf16x2(l[0], l[1]);
    const u32 l23 = pack_bf16x2(l[2], l[3]);
    const size_t o = (size_t)j * NPTS + b4;               // bf16 elem index, 8B-aligned
    *(uint2*)((char*)g_fhi + o * 2) = make_uint2(h01, h23);
    *(uint2*)((char*)g_flo + o * 2) = make_uint2(l01, l23);
}

// ---------------------------------------------------------------------------
// Main: CTA = M-tile of 16 rows = a-pair (a0, a0+1) x 8 RBF bases.
//   Warp w covers K slice [w*96, w*96+96) in 6 ksteps of 16.
//   R7: dual accumulator sets (even/odd kstep) to halve the serialized-HMMA
//   chain; B fragments software-pipelined one kstep ahead; PDL overlap with
//   the prep kernel (griddepcontrol.wait before first B read).
// ---------------------------------------------------------------------------
__global__ void __launch_bounds__(NTHR, 3) conv_main(
    const float* __restrict__ geom,    // [768,3]
    const float* __restrict__ W,       // [8,16,16]
    const float* __restrict__ mu,      // [8]
    const float* __restrict__ gamma,   // [8]
    float scale,
    float* __restrict__ out)           // [768,16]
{
    __shared__ float sD[2 * NPTS];     // distances d[a_local][b]
    __shared__ float sRed[8 * 256];    // per-warp C tiles [w][row][col]
    __shared__ float sG[256];          // reduced G [row][col]

    const int tid  = threadIdx.x;
    const int lane = tid & 31;
    const int warp = tid >> 5;
    const int a0   = blockIdx.x * 2;

    // ---- distances: 1536 values, 6 per thread (independent of prep output)
    {
        const float g0x = __ldg(&geom[a0 * 3]),       g0y = __ldg(&geom[a0 * 3 + 1]),
                    g0z = __ldg(&geom[a0 * 3 + 2]);
        const float g1x = __ldg(&geom[a0 * 3 + 3]),   g1y = __ldg(&geom[a0 * 3 + 4]),
                    g1z = __ldg(&geom[a0 * 3 + 5]);
        #pragma unroll
        for (int q = 0; q < 6; q++) {
            const int v  = tid + q * NTHR;            // 0..1535
            const int aL = v >= NPTS;
            const int b  = v - aL * NPTS;
            const float bx = __ldg(&geom[b * 3]);
            const float by = __ldg(&geom[b * 3 + 1]);
            const float bz = __ldg(&geom[b * 3 + 2]);
            const float dx = bx - (aL ? g1x : g0x);
            const float dy = by - (aL ? g1y : g0y);
            const float dz = bz - (aL ? g1z : g0z);
            float d2 = fmaf(dx, dx, 1e-9f);
            d2 = fmaf(dy, dy, d2);
            d2 = fmaf(dz, dz, d2);
            sD[v] = sqrt_apx(d2);
        }
    }
    __syncthreads();

    // PDL: prep's writes to g_fhi/g_flo must be visible past this point.
    asm volatile("griddepcontrol.wait;" ::: "memory");

    const int g = lane >> 2;           // fragment group = r
    const int t = lane & 3;
    const int c = t * 2;

    // RBF consts for this lane's r=g:  pw = -(kr*d + mr)^2
    const float kr = sqrt_apx(__ldg(gamma + g) * 1.44269504088896f);
    const float mr = -__ldg(mu + g) * kr;

    float accA[8], accB[8];            // dual sets: even/odd ksteps
    #pragma unroll
    for (int k = 0; k < 8; k++) { accA[k] = 0.f; accB[k] = 0.f; }

    const char* fhB = (const char*)g_fhi;
    const char* flB = (const char*)g_flo;
    const int kb0 = warp * 96 + c;

    // ---- prefetch B frags for kstep 0 ----
    u32 bh[8], bl[8];
    {
        const size_t i0 = ((size_t)g * NPTS + kb0) * 2;
        const size_t i1 = i0 + (size_t)8 * NPTS * 2;
        bh[0] = *(const u32*)(fhB + i0);      bh[1] = *(const u32*)(fhB + i0 + 16);
        bh[2] = *(const u32*)(fhB + i1);      bh[3] = *(const u32*)(fhB + i1 + 16);
        bl[0] = *(const u32*)(flB + i0);      bl[1] = *(const u32*)(flB + i0 + 16);
        bl[2] = *(const u32*)(flB + i1);      bl[3] = *(const u32*)(flB + i1 + 16);
    }

    #pragma unroll
    for (int s = 0; s < 6; s++) {
        const int kb = kb0 + s * 16;
        const int cur = (s & 1) ? 4 : 0;   // which half of bh/bl holds this kstep
        const int nxt = 4 - cur;

        // ---- prefetch next kstep's B frags (overlaps the MUFU chain below)
        if (s < 5) {
            const size_t i0 = ((size_t)g * NPTS + kb + 16) * 2;
            const size_t i1 = i0 + (size_t)8 * NPTS * 2;
            bh[nxt]     = *(const u32*)(fhB + i0);
            bh[nxt + 1] = *(const u32*)(fhB + i0 + 16);
            bh[nxt + 2] = *(const u32*)(fhB + i1);
            bh[nxt + 3] = *(const u32*)(fhB + i1 + 16);
            bl[nxt]     = *(const u32*)(flB + i0);
            bl[nxt + 1] = *(const u32*)(flB + i0 + 16);
            bl[nxt + 2] = *(const u32*)(flB + i1);
            bl[nxt + 3] = *(const u32*)(flB + i1 + 16);
        }

        // ---- A fragments (rbf hi/lo) from smem distances ----
        const float2 d00 = *(const float2*)&sD[kb];            // row g   , cols c,c+1
        const float2 d01 = *(const float2*)&sD[kb + 8];        // row g   , cols c+8,c+9
        const float2 d10 = *(const float2*)&sD[NPTS + kb];     // row g+8
        const float2 d11 = *(const float2*)&sD[NPTS + kb + 8];

        float v;
        v = fmaf(d00.x, kr, mr); const float e00x = ex2f(v * (-v));
        v = fmaf(d00.y, kr, mr); const float e00y = ex2f(v * (-v));
        v = fmaf(d10.x, kr, mr); const float e10x = ex2f(v * (-v));
        v = fmaf(d10.y, kr, mr); const float e10y = ex2f(v * (-v));
        v = fmaf(d01.x, kr, mr); const float e01x = ex2f(v * (-v));
        v = fmaf(d01.y, kr, mr); const float e01y = ex2f(v * (-v));
        v = fmaf(d11.x, kr, mr); const float e11x = ex2f(v * (-v));
        v = fmaf(d11.y, kr, mr); const float e11y = ex2f(v * (-v));

        const u32 ah0 = pack_bf16x2(e00x, e00y);
        const u32 ah1 = pack_bf16x2(e10x, e10y);
        const u32 ah2 = pack_bf16x2(e01x, e01y);
        const u32 ah3 = pack_bf16x2(e11x, e11y);

        const u32 al0 = pack_bf16x2(e00x - __uint_as_float(ah0 << 16),
                                    e00y - __uint_as_float(ah0 & 0xFFFF0000u));
        const u32 al1 = pack_bf16x2(e10x - __uint_as_float(ah1 << 16),
                                    e10y - __uint_as_float(ah1 & 0xFFFF0000u));
        const u32 al2 = pack_bf16x2(e01x - __uint_as_float(ah2 << 16),
                                    e01y - __uint_as_float(ah2 & 0xFFFF0000u));
        const u32 al3 = pack_bf16x2(e11x - __uint_as_float(ah3 << 16),
                                    e11y - __uint_as_float(ah3 & 0xFFFF0000u));

        float* acc = (s & 1) ? accB : accA;   // s is compile-time (full unroll)
        mma16816(acc[0], acc[1], acc[2], acc[3], ah0, ah1, ah2, ah3, bh[cur], bh[cur+1]);
        mma16816(acc[4], acc[5], acc[6], acc[7], ah0, ah1, ah2, ah3, bh[cur+2], bh[cur+3]);
        mma16816(acc[0], acc[1], acc[2], acc[3], al0, al1, al2, al3, bh[cur], bh[cur+1]);
        mma16816(acc[4], acc[5], acc[6], acc[7], al0, al1, al2, al3, bh[cur+2], bh[cur+3]);
        mma16816(acc[0], acc[1], acc[2], acc[3], ah0, ah1, ah2, ah3, bl[cur], bl[cur+1]);
        mma16816(acc[4], acc[5], acc[6], acc[7], ah0, ah1, ah2, ah3, bl[cur+2], bl[cur+3]);
    }

    // ---- merge dual sets ----
    #pragma unroll
    for (int k = 0; k < 8; k++) accA[k] += accB[k];

    // ---- stash per-warp C tile: sRed[w][row][col] ----
    {
        float* rb = sRed + warp * 256;
        *(float2*)&rb[g * 16 + c]            = make_float2(accA[0], accA[1]);
        *(float2*)&rb[(g + 8) * 16 + c]      = make_float2(accA[2], accA[3]);
        *(float2*)&rb[g * 16 + 8 + c]        = make_float2(accA[4], accA[5]);
        *(float2*)&rb[(g + 8) * 16 + 8 + c]  = make_float2(accA[6], accA[7]);
    }
    __syncthreads();

    // ---- reduce over 8 warps ----
    {
        float s = 0.f;
        #pragma unroll
        for (int w = 0; w < 8; w++) s += sRed[w * 256 + tid];
        sG[tid] = s;
    }
    __syncthreads();

    // ---- W contraction: thread = (a_local, i, r); reduce r via shfl ----
    {
        const int r2 = tid & 7;
        const int i  = (tid >> 3) & 15;
        const int aL = tid >> 7;
        const float* gp = sG + (aL * 8 + r2) * 16;
        const float4* wp = (const float4*)W + r2 * 64 + i * 4;
        float a = 0.f;
        #pragma unroll
        for (int q = 0; q < 4; q++) {
            const float4 g4 = *(const float4*)(gp + q * 4);
            const float4 w4 = __ldg(wp + q);
            a = fmaf(w4.x, g4.x, a);
            a = fmaf(w4.y, g4.y, a);
            a = fmaf(w4.z, g4.z, a);
            a = fmaf(w4.w, g4.w, a);
        }
        a += __shfl_xor_sync(0xffffffffu, a, 1);
        a += __shfl_xor_sync(0xffffffffu, a, 2);
        a += __shfl_xor_sync(0xffffffffu, a, 4);
        if (r2 == 0) out[(a0 + aL) * 16 + i] = a * scale;
    }
}

// ---------------------------------------------------------------------------
extern "C" void kernel_launch(void* const* d_in, const int* in_sizes, int n_in,
                              void* d_out, int out_size)
{
    const float* feat  = (const float*)d_in[0];   // [1,768,16]
    const float* geom  = (const float*)d_in[1];   // [1,768,3]
    const float* W     = (const float*)d_in[2];   // [8,16,16]
    const float* mu    = (const float*)d_in[3];   // [8]
    const float* gamma = (const float*)d_in[4];   // [8]
    float* out = (float*)d_out;

    const int n_norm = in_sizes[1] / 3;
    const float scale = 1.0f / sqrtf((float)n_norm);

    conv_prep<<<12, NTHR>>>(feat);

    // PDL launch: overlap conv_main's launch + distance prologue with prep.
    cudaLaunchConfig_t cfg = {};
    cfg.gridDim  = dim3(NTILES);
    cfg.blockDim = dim3(NTHR);
    cfg.dynamicSmemBytes = 0;
    cfg.stream = 0;
    cudaLaunchAttribute at[1];
    at[0].id = cudaLaunchAttributeProgrammaticStreamSerialization;
    at[0].val.programmaticStreamSerializationAllowed = 1;
    cfg.attrs = at;
    cfg.numAttrs = 1;
    cudaLaunchKernelEx(&cfg, conv_main, geom, W, mu, gamma, scale, out);
}

// round 8
// speedup vs baseline: 1.7413x; 1.3488x over previous
#include <cuda_runtime.h>
#include <cuda_bf16.h>
#include <cstdint>

// Fixed shape: B=1, N=768, C_IN=C_OUT=16, R=8
#define NPTS   768
#define NTILES 384          // M-tiles of 16 rows (2 a's x 8 r); one CTA each
#define NTHR   256
#define NKS    48           // total ksteps (K=768 / 16)

typedef unsigned int u32;

// B fragments pre-arranged in register order by conv_prep:
//   g_bfragH[ks][lane] = {bh00, bh01, bh10, bh11}  (uint4)
//   g_bfragL[ks][lane] = {bl00, bl01, bl10, bl11}
// Identical for every CTA (K-slices are global) -> perfect L1 reuse.
__device__ uint4 g_bfragH[NKS * 32];
__device__ uint4 g_bfragL[NKS * 32];

__device__ __forceinline__ u32 pack_bf16x2(float lo, float hi) {
    u32 d;
    asm("cvt.rn.bf16x2.f32 %0, %1, %2;" : "=r"(d) : "f"(hi), "f"(lo));
    return d;
}
__device__ __forceinline__ float ex2f(float x) {
    float e;
    asm("ex2.approx.f32 %0, %1;" : "=f"(e) : "f"(x));
    return e;
}
__device__ __forceinline__ float sqrt_apx(float x) {
    float s;
    asm("sqrt.approx.f32 %0, %1;" : "=f"(s) : "f"(x));
    return s;
}
// D(16x8,f32) += A(16x16,row,bf16) * B(16x8,col,bf16)
__device__ __forceinline__ void mma16816(float& c0, float& c1, float& c2, float& c3,
                                         u32 a0, u32 a1, u32 a2, u32 a3,
                                         u32 b0, u32 b1) {
    asm("mma.sync.aligned.m16n8k16.row.col.f32.bf16.bf16.f32 "
        "{%0,%1,%2,%3}, {%4,%5,%6,%7}, {%8,%9}, {%0,%1,%2,%3};"
        : "+f"(c0), "+f"(c1), "+f"(c2), "+f"(c3)
        : "r"(a0), "r"(a1), "r"(a2), "r"(a3), "r"(b0), "r"(b1));
}

// ---------------------------------------------------------------------------
// Prep: build hi/lo bf16 B fragments directly in mma-fragment order.
// Thread = (ks, lane); lane decodes as g=lane>>2 (n-col), t=lane&3 (k-pair).
//   b-reg0 covers k = k0,k0+1 ; b-reg1 covers k = k0+8,k0+9 (PTX m16n8k16).
// ---------------------------------------------------------------------------
__global__ void __launch_bounds__(NTHR) conv_prep(const float* __restrict__ feat)
{
    const int idx  = blockIdx.x * NTHR + threadIdx.x;     // 0..1535
    const int ks   = idx >> 5;
    const int lane = idx & 31;
    const int g    = lane >> 2;
    const int k0   = ks * 16 + (lane & 3) * 2;

    float f[8];                                           // [col0 k0,k0+1,k0+8,k0+9 | col1 ...]
    #pragma unroll
    for (int q = 0; q < 2; q++) {                         // q=0: col g, q=1: col g+8
        const int j = g + q * 8;
        f[q * 4 + 0] = __ldg(&feat[(k0)     * 16 + j]);
        f[q * 4 + 1] = __ldg(&feat[(k0 + 1) * 16 + j]);
        f[q * 4 + 2] = __ldg(&feat[(k0 + 8) * 16 + j]);
        f[q * 4 + 3] = __ldg(&feat[(k0 + 9) * 16 + j]);
    }
    float h[8], l[8];
    #pragma unroll
    for (int q = 0; q < 8; q++) {
        h[q] = __bfloat162float(__float2bfloat16(f[q]));
        l[q] = f[q] - h[q];
    }
    uint4 BH, BL;
    BH.x = pack_bf16x2(h[0], h[1]);  BH.y = pack_bf16x2(h[2], h[3]);
    BH.z = pack_bf16x2(h[4], h[5]);  BH.w = pack_bf16x2(h[6], h[7]);
    BL.x = pack_bf16x2(l[0], l[1]);  BL.y = pack_bf16x2(l[2], l[3]);
    BL.z = pack_bf16x2(l[4], l[5]);  BL.w = pack_bf16x2(l[6], l[7]);
    g_bfragH[ks * 32 + lane] = BH;
    g_bfragL[ks * 32 + lane] = BL;
}

// ---------------------------------------------------------------------------
// Main: CTA = M-tile of 16 rows = a-pair (a0, a0+1) x 8 RBF bases.
//   Warp w covers K slice [w*96, w*96+96) in 6 ksteps of 16.
//   B fragments: 2 coalesced LDG.128 per kstep from g_bfragH/L (prefetched
//   one kstep ahead). Dual accumulator sets. PDL overlap with conv_prep.
// ---------------------------------------------------------------------------
__global__ void __launch_bounds__(NTHR, 3) conv_main(
    const float* __restrict__ geom,    // [768,3]
    const float* __restrict__ W,       // [8,16,16]
    const float* __restrict__ mu,      // [8]
    const float* __restrict__ gamma,   // [8]
    float scale,
    float* __restrict__ out)           // [768,16]
{
    __shared__ float sD[2 * NPTS];     // distances d[a_local][b]
    __shared__ float sRed[8 * 256];    // per-warp C tiles [w][row][col]
    __shared__ float sG[256];          // reduced G [row][col]

    const int tid  = threadIdx.x;
    const int lane = tid & 31;
    const int warp = tid >> 5;
    const int a0   = blockIdx.x * 2;

    // ---- distances: 1536 values, 6 per thread (independent of prep output)
    {
        const float g0x = __ldg(&geom[a0 * 3]),       g0y = __ldg(&geom[a0 * 3 + 1]),
                    g0z = __ldg(&geom[a0 * 3 + 2]);
        const float g1x = __ldg(&geom[a0 * 3 + 3]),   g1y = __ldg(&geom[a0 * 3 + 4]),
                    g1z = __ldg(&geom[a0 * 3 + 5]);
        #pragma unroll
        for (int q = 0; q < 6; q++) {
            const int v  = tid + q * NTHR;            // 0..1535
            const int aL = v >= NPTS;
            const int b  = v - aL * NPTS;
            const float bx = __ldg(&geom[b * 3]);
            const float by = __ldg(&geom[b * 3 + 1]);
            const float bz = __ldg(&geom[b * 3 + 2]);
            const float dx = bx - (aL ? g1x : g0x);
            const float dy = by - (aL ? g1y : g0y);
            const float dz = bz - (aL ? g1z : g0z);
            float d2 = fmaf(dx, dx, 1e-9f);
            d2 = fmaf(dy, dy, d2);
            d2 = fmaf(dz, dz, d2);
            sD[v] = sqrt_apx(d2);
        }
    }
    __syncthreads();

    // PDL: prep's writes to g_bfragH/L must be visible past this point.
    asm volatile("griddepcontrol.wait;" ::: "memory");

    const int g = lane >> 2;           // fragment group = r
    const int c = (lane & 3) * 2;

    // RBF consts for this lane's r=g:  pw = -(kr*d + mr)^2
    const float kr = sqrt_apx(__ldg(gamma + g) * 1.44269504088896f);
    const float mr = -__ldg(mu + g) * kr;

    float accA[8], accB[8];            // dual sets: even/odd ksteps
    #pragma unroll
    for (int k = 0; k < 8; k++) { accA[k] = 0.f; accB[k] = 0.f; }

    const int kb0 = warp * 96 + c;
    const uint4* bHp = g_bfragH + (warp * 6) * 32 + lane;
    const uint4* bLp = g_bfragL + (warp * 6) * 32 + lane;

    // ---- prefetch B frags for kstep 0 (coalesced LDG.128 x2) ----
    uint4 BH[2], BL[2];
    BH[0] = bHp[0];
    BL[0] = bLp[0];

    #pragma unroll
    for (int s = 0; s < 6; s++) {
        const int kb  = kb0 + s * 16;
        const int cur = s & 1;
        const int nxt = cur ^ 1;

        // prefetch next kstep (overlaps the MUFU chain below)
        if (s < 5) {
            BH[nxt] = bHp[(s + 1) * 32];
            BL[nxt] = bLp[(s + 1) * 32];
        }

        // ---- A fragments (rbf hi/lo) from smem distances ----
        const float2 d00 = *(const float2*)&sD[kb];            // row g   , cols c,c+1
        const float2 d01 = *(const float2*)&sD[kb + 8];        // row g   , cols c+8,c+9
        const float2 d10 = *(const float2*)&sD[NPTS + kb];     // row g+8
        const float2 d11 = *(const float2*)&sD[NPTS + kb + 8];

        float v;
        v = fmaf(d00.x, kr, mr); const float e00x = ex2f(v * (-v));
        v = fmaf(d00.y, kr, mr); const float e00y = ex2f(v * (-v));
        v = fmaf(d10.x, kr, mr); const float e10x = ex2f(v * (-v));
        v = fmaf(d10.y, kr, mr); const float e10y = ex2f(v * (-v));
        v = fmaf(d01.x, kr, mr); const float e01x = ex2f(v * (-v));
        v = fmaf(d01.y, kr, mr); const float e01y = ex2f(v * (-v));
        v = fmaf(d11.x, kr, mr); const float e11x = ex2f(v * (-v));
        v = fmaf(d11.y, kr, mr); const float e11y = ex2f(v * (-v));

        const u32 ah0 = pack_bf16x2(e00x, e00y);
        const u32 ah1 = pack_bf16x2(e10x, e10y);
        const u32 ah2 = pack_bf16x2(e01x, e01y);
        const u32 ah3 = pack_bf16x2(e11x, e11y);

        const u32 al0 = pack_bf16x2(e00x - __uint_as_float(ah0 << 16),
                                    e00y - __uint_as_float(ah0 & 0xFFFF0000u));
        const u32 al1 = pack_bf16x2(e10x - __uint_as_float(ah1 << 16),
                                    e10y - __uint_as_float(ah1 & 0xFFFF0000u));
        const u32 al2 = pack_bf16x2(e01x - __uint_as_float(ah2 << 16),
                                    e01y - __uint_as_float(ah2 & 0xFFFF0000u));
        const u32 al3 = pack_bf16x2(e11x - __uint_as_float(ah3 << 16),
                                    e11y - __uint_as_float(ah3 & 0xFFFF0000u));

        float* acc = (s & 1) ? accB : accA;   // compile-time (fully unrolled)
        const uint4 bh = BH[cur], bl = BL[cur];
        mma16816(acc[0], acc[1], acc[2], acc[3], ah0, ah1, ah2, ah3, bh.x, bh.y);
        mma16816(acc[4], acc[5], acc[6], acc[7], ah0, ah1, ah2, ah3, bh.z, bh.w);
        mma16816(acc[0], acc[1], acc[2], acc[3], al0, al1, al2, al3, bh.x, bh.y);
        mma16816(acc[4], acc[5], acc[6], acc[7], al0, al1, al2, al3, bh.z, bh.w);
        mma16816(acc[0], acc[1], acc[2], acc[3], ah0, ah1, ah2, ah3, bl.x, bl.y);
        mma16816(acc[4], acc[5], acc[6], acc[7], ah0, ah1, ah2, ah3, bl.z, bl.w);
    }

    // ---- merge dual sets ----
    #pragma unroll
    for (int k = 0; k < 8; k++) accA[k] += accB[k];

    // ---- stash per-warp C tile: sRed[w][row][col] ----
    {
        float* rb = sRed + warp * 256;
        *(float2*)&rb[g * 16 + c]            = make_float2(accA[0], accA[1]);
        *(float2*)&rb[(g + 8) * 16 + c]      = make_float2(accA[2], accA[3]);
        *(float2*)&rb[g * 16 + 8 + c]        = make_float2(accA[4], accA[5]);
        *(float2*)&rb[(g + 8) * 16 + 8 + c]  = make_float2(accA[6], accA[7]);
    }
    __syncthreads();

    // ---- reduce over 8 warps ----
    {
        float s = 0.f;
        #pragma unroll
        for (int w = 0; w < 8; w++) s += sRed[w * 256 + tid];
        sG[tid] = s;
    }
    __syncthreads();

    // ---- W contraction: thread = (a_local, i, r); reduce r via shfl ----
    {
        const int r2 = tid & 7;
        const int i  = (tid >> 3) & 15;
        const int aL = tid >> 7;
        const float* gp = sG + (aL * 8 + r2) * 16;
        const float4* wp = (const float4*)W + r2 * 64 + i * 4;
        float a = 0.f;
        #pragma unroll
        for (int q = 0; q < 4; q++) {
            const float4 g4 = *(const float4*)(gp + q * 4);
            const float4 w4 = __ldg(wp + q);
            a = fmaf(w4.x, g4.x, a);
            a = fmaf(w4.y, g4.y, a);
            a = fmaf(w4.z, g4.z, a);
            a = fmaf(w4.w, g4.w, a);
        }
        a += __shfl_xor_sync(0xffffffffu, a, 1);
        a += __shfl_xor_sync(0xffffffffu, a, 2);
        a += __shfl_xor_sync(0xffffffffu, a, 4);
        if (r2 == 0) out[(a0 + aL) * 16 + i] = a * scale;
    }
}

// ---------------------------------------------------------------------------
extern "C" void kernel_launch(void* const* d_in, const int* in_sizes, int n_in,
                              void* d_out, int out_size)
{
    const float* feat  = (const float*)d_in[0];   // [1,768,16]
    const float* geom  = (const float*)d_in[1];   // [1,768,3]
    const float* W     = (const float*)d_in[2];   // [8,16,16]
    const float* mu    = (const float*)d_in[3];   // [8]
    const float* gamma = (const float*)d_in[4];   // [8]
    float* out = (float*)d_out;

    const int n_norm = in_sizes[1] / 3;
    const float scale = 1.0f / sqrtf((float)n_norm);

    conv_prep<<<6, NTHR>>>(feat);

    // PDL launch: overlap conv_main's launch + distance prologue with prep.
    cudaLaunchConfig_t cfg = {};
    cfg.gridDim  = dim3(NTILES);
    cfg.blockDim = dim3(NTHR);
    cfg.dynamicSmemBytes = 0;
    cfg.stream = 0;
    cudaLaunchAttribute at[1];
    at[0].id = cudaLaunchAttributeProgrammaticStreamSerialization;
    at[0].val.programmaticStreamSerializationAllowed = 1;
    cfg.attrs = at;
    cfg.numAttrs = 1;
    cudaLaunchKernelEx(&cfg, conv_main, geom, W, mu, gamma, scale, out);
}